// round 4
// baseline (speedup 1.0000x reference)
#include <cuda_runtime.h>
#include <math.h>

#define J   23
#define TPB 256
#define PI_F 3.14159265358979323846f

__constant__ int cPAR[J] = {-1,0,1,1,3,4,5,4,7,4,9,1,11,12,13,12,15,12,17,0,19,0,21};

static __device__ float4 g_A[J * 3];
static __device__ float  g_const[4];

// ---------------- Prep: one warp. pose -> Rodrigues -> FK -> A + small outputs ----------------
__global__ void __launch_bounds__(32) prep_kernel(
    const float* __restrict__ jr,
    const float* __restrict__ p0, const float* __restrict__ p1,
    const float* __restrict__ p2, const float* __restrict__ p3,
    const float* __restrict__ p4, const float* __restrict__ p5,
    const float* __restrict__ p12, const float* __restrict__ p13,
    const float* __restrict__ disp, const float* __restrict__ scale,
    const float* __restrict__ loc,
    float* __restrict__ out, int B, int V)
{
    __shared__ float s_Tl[J * 12];
    __shared__ float s_G[J * 12];
    __shared__ float s_pose[J * 3];

    const int tid = threadIdx.x;

    float cst = 0.f, ox = 0.f, oy = 0.f, oz = 0.f;
    if (tid == 31) {
        cst = 0.0035f * scale[0];
        ox = loc[0] + 0.1f * tanhf(disp[0]);
        oy = loc[1] + 0.1f * tanhf(disp[1]);
        oz = loc[2] + 0.1f * tanhf(disp[2]);
        g_const[0] = cst; g_const[1] = ox; g_const[2] = oy; g_const[3] = oz;
    }

    if (tid < J) {
        float fac = 0.f, sy = 1.f, sz = 1.f;
        const float* pp = p0;
        bool has = true;
        switch (tid) {
            case 0:  fac = PI_F / 2.f; pp = p0;  break;
            case 1:  fac = PI_F / 4.f; pp = p1;  break;
            case 2:  fac = PI_F / 9.f; pp = p2;  break;
            case 3:  fac = PI_F / 3.f; pp = p3;  break;
            case 4:  fac = PI_F / 3.f; pp = p4;  break;
            case 5:  fac = PI_F / 3.f; pp = p5;  break;
            case 11: fac = PI_F / 3.f; pp = p3;  sy = -1.f; sz = -1.f; break;
            case 12: fac = PI_F / 3.f; pp = p12; break;
            case 13: fac = PI_F / 3.f; pp = p13; break;
            default: has = false;
        }
        float px = 0.f, py = 0.f, pz = 0.f;
        if (has) {
            px = fac * tanhf(pp[0]);
            py = sy * fac * tanhf(pp[1]);
            pz = sz * fac * tanhf(pp[2]);
        }
        s_pose[3 * tid + 0] = px;
        s_pose[3 * tid + 1] = py;
        s_pose[3 * tid + 2] = pz;

        float ang = sqrtf(px * px + py * py + pz * pz + 1e-12f);
        float inv = 1.f / ang;
        float x = px * inv, y = py * inv, z = pz * inv;
        float s = sinf(ang), c = cosf(ang), t = 1.f - c;
        float* T = &s_Tl[tid * 12];
        T[0] = 1.f + t * (-(z * z) - (y * y));
        T[1] = -s * z + t * (x * y);
        T[2] =  s * y + t * (x * z);
        T[4] =  s * z + t * (x * y);
        T[5] = 1.f + t * (-(z * z) - (x * x));
        T[6] = -s * x + t * (y * z);
        T[8] = -s * y + t * (x * z);
        T[9] =  s * x + t * (y * z);
        T[10] = 1.f + t * (-(y * y) - (x * x));

        int par = cPAR[tid];
        float jx = jr[3 * tid], jy = jr[3 * tid + 1], jz = jr[3 * tid + 2];
        if (par >= 0) { jx -= jr[3 * par]; jy -= jr[3 * par + 1]; jz -= jr[3 * par + 2]; }
        T[3] = jx; T[7] = jy; T[11] = jz;
    }
    __syncwarp();

    if (tid < 12) s_G[tid] = s_Tl[tid];
    __syncwarp();
    #pragma unroll
    for (int j = 1; j < J; j++) {
        const int p = cPAR[j];
        if (tid < 12) {
            const int r = tid >> 2, c = tid & 3;
            const float* gp = &s_G[p * 12 + r * 4];
            const float* tl = &s_Tl[j * 12];
            float v = gp[0] * tl[0 * 4 + c]
                    + gp[1] * tl[1 * 4 + c]
                    + gp[2] * tl[2 * 4 + c];
            if (c == 3) v += gp[3];
            s_G[j * 12 + tid] = v;
        }
        __syncwarp();
    }

    if (tid < J) {
        const float* g = &s_G[tid * 12];
        float jx = jr[3 * tid], jy = jr[3 * tid + 1], jz = jr[3 * tid + 2];
        float tcx = g[0] * jx + g[1] * jy + g[2] * jz;
        float tcy = g[4] * jx + g[5] * jy + g[6] * jz;
        float tcz = g[8] * jx + g[9] * jy + g[10] * jz;
        g_A[tid * 3 + 0] = make_float4(g[0], g[1], g[2],  g[3]  - tcx);
        g_A[tid * 3 + 1] = make_float4(g[4], g[5], g[6],  g[7]  - tcy);
        g_A[tid * 3 + 2] = make_float4(g[8], g[9], g[10], g[11] - tcz);
    }

    const long V3 = 3L * (long)V;
    const long base = (long)B * V3;
    if (tid < J) {
        out[base + 3 * tid + 0] = s_pose[3 * tid + 0];
        out[base + 3 * tid + 1] = s_pose[3 * tid + 1];
        out[base + 3 * tid + 2] = s_pose[3 * tid + 2];
    }
    __syncwarp();
    if (tid == 31) {
        for (int j = 0; j < J; j++) {
            out[base + 69 + 3 * j + 0] = fmaf(cst, s_G[j * 12 + 3],  ox);
            out[base + 69 + 3 * j + 1] = fmaf(cst, s_G[j * 12 + 7],  oy);
            out[base + 69 + 3 * j + 2] = fmaf(cst, s_G[j * 12 + 11], oz);
        }
        out[base + 138] = scale[0];
        out[base + 139] = disp[0];
        out[base + 140] = disp[1];
        out[base + 141] = disp[2];
    }
}

// ---------------- LBS: 4 vertices per thread, fully vectorized, no input staging ----------------
__global__ void __launch_bounds__(TPB, 1) lbs_kernel(
    const float* __restrict__ vt,
    const float* __restrict__ sk,
    const float* __restrict__ la,
    float* __restrict__ out, int V, int B)
{
    __shared__ float4 s_A4[J * 3];
    __shared__ float  s_c[4];

    const int tid = threadIdx.x;
    if (tid < J * 3) s_A4[tid] = g_A[tid];
    if (tid >= 96 && tid < 100) s_c[tid - 96] = g_const[tid - 96];
    __syncthreads();

    const long t = (long)blockIdx.x * TPB + tid;
    const long nq = (long)(V >> 2);           // full quads
    const long V3 = 3L * (long)V;
    const long offLa = (long)B * V3 + 142;

    if (t < nq) {
        const long v0 = t * 4;

        // ---- loads ----
        float4 skq[23];
        const float4* sk4 = (const float4*)(sk + v0 * 23);
        #pragma unroll
        for (int i = 0; i < 23; i++) skq[i] = __ldcs(sk4 + i);

        float4 vtq[3], laq[3];
        const float4* vt4 = (const float4*)(vt + v0 * 3);
        const float4* la4 = (const float4*)(la + v0 * 3);
        #pragma unroll
        for (int i = 0; i < 3; i++) { vtq[i] = __ldcs(vt4 + i); laq[i] = __ldcs(la4 + i); }

        const float* laf = (const float*)laq;
        const float* vtf = (const float*)vtq;

        // la passthrough immediately (frees laq -> shorter liveness)
        {
            float2* gl2 = (float2*)(out + offLa + v0 * 3);
            const float2* l2 = (const float2*)laq;
            #pragma unroll
            for (int i = 0; i < 6; i++) __stcs(gl2 + i, l2[i]);
        }

        // vh per vertex
        float vh[4][3];
        #pragma unroll
        for (int a = 0; a < 4; a++) {
            #pragma unroll
            for (int k = 0; k < 3; k++)
                vh[a][k] = vtf[3 * a + k] + 0.1f * tanhf(laf[3 * a + k]);
        }

        // ---- accumulate T = sum_j w_j A_j for 4 vertices ----
        const float* w = (const float*)skq;
        float4 t0[4], t1[4], t2[4];
        #pragma unroll
        for (int a = 0; a < 4; a++) {
            t0[a] = make_float4(0.f, 0.f, 0.f, 0.f);
            t1[a] = make_float4(0.f, 0.f, 0.f, 0.f);
            t2[a] = make_float4(0.f, 0.f, 0.f, 0.f);
        }

        #pragma unroll
        for (int j = 0; j < J; j++) {
            const float4 a0 = s_A4[3 * j + 0];
            const float4 a1 = s_A4[3 * j + 1];
            const float4 a2 = s_A4[3 * j + 2];
            #pragma unroll
            for (int a = 0; a < 4; a++) {
                const float wj = w[a * 23 + j];
                t0[a].x = fmaf(wj, a0.x, t0[a].x); t0[a].y = fmaf(wj, a0.y, t0[a].y);
                t0[a].z = fmaf(wj, a0.z, t0[a].z); t0[a].w = fmaf(wj, a0.w, t0[a].w);
                t1[a].x = fmaf(wj, a1.x, t1[a].x); t1[a].y = fmaf(wj, a1.y, t1[a].y);
                t1[a].z = fmaf(wj, a1.z, t1[a].z); t1[a].w = fmaf(wj, a1.w, t1[a].w);
                t2[a].x = fmaf(wj, a2.x, t2[a].x); t2[a].y = fmaf(wj, a2.y, t2[a].y);
                t2[a].z = fmaf(wj, a2.z, t2[a].z); t2[a].w = fmaf(wj, a2.w, t2[a].w);
            }
        }

        // ---- epilogue: apply transform, scale/offset, store ----
        const float c = s_c[0];
        float res[12];
        #pragma unroll
        for (int a = 0; a < 4; a++) {
            float x = fmaf(t0[a].x, vh[a][0], fmaf(t0[a].y, vh[a][1], fmaf(t0[a].z, vh[a][2], t0[a].w)));
            float y = fmaf(t1[a].x, vh[a][0], fmaf(t1[a].y, vh[a][1], fmaf(t1[a].z, vh[a][2], t1[a].w)));
            float z = fmaf(t2[a].x, vh[a][0], fmaf(t2[a].y, vh[a][1], fmaf(t2[a].z, vh[a][2], t2[a].w)));
            res[3 * a + 0] = fmaf(c, x, s_c[1]);
            res[3 * a + 1] = fmaf(c, y, s_c[2]);
            res[3 * a + 2] = fmaf(c, z, s_c[3]);
        }

        const float4* r4 = (const float4*)res;
        #pragma unroll 4
        for (int b = 0; b < B; b++) {
            float4* go = (float4*)(out + (long)b * V3 + v0 * 3);
            __stcs(go + 0, r4[0]);
            __stcs(go + 1, r4[1]);
            __stcs(go + 2, r4[2]);
        }
    }

    // remainder vertices (V % 4), handled scalar by first threads of block 0
    const int rem = V & 3;
    if (blockIdx.x == 0 && tid < rem) {
        const long v = (long)(V - rem) + tid;
        float l0 = la[3 * v + 0], l1 = la[3 * v + 1], l2v = la[3 * v + 2];
        float vx = vt[3 * v + 0] + 0.1f * tanhf(l0);
        float vy = vt[3 * v + 1] + 0.1f * tanhf(l1);
        float vz = vt[3 * v + 2] + 0.1f * tanhf(l2v);
        float4 t0 = make_float4(0,0,0,0), t1 = make_float4(0,0,0,0), t2 = make_float4(0,0,0,0);
        #pragma unroll
        for (int j = 0; j < J; j++) {
            float wj = sk[23 * v + j];
            float4 a0 = s_A4[3*j+0], a1 = s_A4[3*j+1], a2 = s_A4[3*j+2];
            t0.x = fmaf(wj,a0.x,t0.x); t0.y = fmaf(wj,a0.y,t0.y); t0.z = fmaf(wj,a0.z,t0.z); t0.w = fmaf(wj,a0.w,t0.w);
            t1.x = fmaf(wj,a1.x,t1.x); t1.y = fmaf(wj,a1.y,t1.y); t1.z = fmaf(wj,a1.z,t1.z); t1.w = fmaf(wj,a1.w,t1.w);
            t2.x = fmaf(wj,a2.x,t2.x); t2.y = fmaf(wj,a2.y,t2.y); t2.z = fmaf(wj,a2.z,t2.z); t2.w = fmaf(wj,a2.w,t2.w);
        }
        float x = fmaf(t0.x,vx,fmaf(t0.y,vy,fmaf(t0.z,vz,t0.w)));
        float y = fmaf(t1.x,vx,fmaf(t1.y,vy,fmaf(t1.z,vz,t1.w)));
        float z = fmaf(t2.x,vx,fmaf(t2.y,vy,fmaf(t2.z,vz,t2.w)));
        float c = s_c[0];
        float rx = fmaf(c,x,s_c[1]), ry = fmaf(c,y,s_c[2]), rz = fmaf(c,z,s_c[3]);
        for (int b = 0; b < B; b++) {
            out[(long)b * V3 + 3 * v + 0] = rx;
            out[(long)b * V3 + 3 * v + 1] = ry;
            out[(long)b * V3 + 3 * v + 2] = rz;
        }
        out[offLa + 3 * v + 0] = l0;
        out[offLa + 3 * v + 1] = l1;
        out[offLa + 3 * v + 2] = l2v;
    }
}

extern "C" void kernel_launch(void* const* d_in, const int* in_sizes, int n_in,
                              void* d_out, int out_size)
{
    const float* vt    = (const float*)d_in[0];
    const float* sk    = (const float*)d_in[1];
    const float* jr    = (const float*)d_in[2];
    const float* p0    = (const float*)d_in[3];
    const float* p1    = (const float*)d_in[4];
    const float* p2    = (const float*)d_in[5];
    const float* p3    = (const float*)d_in[6];
    const float* p4    = (const float*)d_in[7];
    const float* p5    = (const float*)d_in[8];
    const float* p12   = (const float*)d_in[9];
    const float* p13   = (const float*)d_in[10];
    const float* la    = (const float*)d_in[11];
    const float* disp  = (const float*)d_in[12];
    const float* scale = (const float*)d_in[13];
    const float* loc   = (const float*)d_in[14];
    float* out = (float*)d_out;

    int V = in_sizes[0] / 3;
    long fixed = 69L + 69L + 1L + 3L + 3L * (long)V;
    int B = (int)(((long)out_size - fixed) / (3L * (long)V));

    prep_kernel<<<1, 32>>>(jr, p0, p1, p2, p3, p4, p5, p12, p13,
                           disp, scale, loc, out, B, V);

    int nq = V >> 2;
    int blocks = (nq + TPB - 1) / TPB;
    if (blocks < 1) blocks = 1;
    lbs_kernel<<<blocks, TPB>>>(vt, sk, la, out, V, B);
}